// round 11
// baseline (speedup 1.0000x reference)
#include <cuda_runtime.h>
#include <cuda_fp16.h>

// ---------------------------------------------------------------------------
// CrossCBR propagation, D=64, num_layers=2 (fixed by setup_inputs).
// CSR-gather formulation, fp16-payload edition:
//   - feature rows gathered as half (128B/row) — halves LTS traffic, which
//     R6 showed to be the binding constraint (gathers at the LTS ceiling)
//   - ALL accumulation, L2-norms, and the additive accumulators stay fp32
//   - layer-2 results stream directly into d_out (fp32)
// Launches: memset, cvt, hist, scan x3, ssort, gatherL1, gatherL2, bi  (10)
// ---------------------------------------------------------------------------

#define NU 100000
#define NI 200000
#define NB 50000

// ---- bin bases in the concatenated histogram ------------------------------
#define B_UIU 0        // ui edges grouped by user   (store item)   NU bins
#define B_UII 100000   // ui edges grouped by item   (store user)   NI bins
#define B_UBU 300000   // ub edges grouped by user   (store bundle) NU bins
#define B_UBB 400000   // ub edges grouped by bundle (store user)   NB bins
#define B_BIB 450000   // bi edges grouped by bundle (store item)   NB bins
#define NROWS_PROP 450000
#define TOTBINS 500000
#define TOTEDGE 4000000

#define SCAN_NBLK 489     // ceil(500000/1024)

// ---- half arena offsets (in half units; rows are 64 halves = 16 uint2) ----
#define H_USERS  0UL            // 6.4M
#define H_ITEMS  6400000UL      // 12.8M
#define H_BUND   19200000UL     // 3.2M
#define H_FU1UI  22400000UL     // 6.4M   ui layer-1 user feats
#define H_FI1UI  28800000UL     // 12.8M  ui layer-1 item feats
#define H_FU1UB  41600000UL     // 6.4M   ub layer-1 user feats
#define H_FB1UB  48000000UL     // 3.2M   ub layer-1 bundle feats
#define H_ILI    51200000UL     // 12.8M  IL_items (feeds bi)
#define HALF_TOTAL 64000000UL

// ---- float arena offsets (fp32 accumulators = layer-2 additive bases) -----
#define F_ACCUIL 0UL            // 6.4M
#define F_ACCI   6400000UL      // 12.8M
#define F_ACCUBL 19200000UL     // 6.4M
#define F_ACCB   25600000UL     // 3.2M
#define FLOAT_TOTAL 28800000UL

__device__ __half g_halves[HALF_TOTAL];
__device__ float  g_floats[FLOAT_TOTAL];
__device__ int    g_bins[TOTBINS];
__device__ int    g_rowptr[TOTBINS + 1];
__device__ int    g_cursor[TOTBINS];
__device__ int    g_sorted[TOTEDGE];
__device__ int    g_bsums[512];

static inline int div_up(long long a, int b) { return (int)((a + b - 1) / b); }

// ---- half4 <-> float4 helpers ---------------------------------------------
__device__ __forceinline__ void hacc4(float4& a, uint2 v) {
    __half2 h0 = *reinterpret_cast<__half2*>(&v.x);
    __half2 h1 = *reinterpret_cast<__half2*>(&v.y);
    float2 f0 = __half22float2(h0);
    float2 f1 = __half22float2(h1);
    a.x += f0.x; a.y += f0.y; a.z += f1.x; a.w += f1.y;
}

__device__ __forceinline__ uint2 f4_to_h4(float4 v) {
    __half2 h0 = __floats2half2_rn(v.x, v.y);
    __half2 h1 = __floats2half2_rn(v.z, v.w);
    uint2 o;
    o.x = *reinterpret_cast<unsigned*>(&h0);
    o.y = *reinterpret_cast<unsigned*>(&h1);
    return o;
}

// ===========================================================================
// fp32 -> fp16 conversion of the three input tables (one launch)
// ===========================================================================
__global__ void cvt_k(const float4* __restrict__ u, const float4* __restrict__ it,
                      const float4* __restrict__ b,
                      uint2* __restrict__ hu, uint2* __restrict__ hi,
                      uint2* __restrict__ hb) {
    int i = blockIdx.x * 256 + threadIdx.x;
    const float4* s; uint2* d; int j;
    if (i < NU * 16)                  { s = u;  d = hu; j = i; }
    else if (i < (NU + NI) * 16)      { s = it; d = hi; j = i - NU * 16; }
    else if (i < (NU + NI + NB) * 16) { s = b;  d = hb; j = i - (NU + NI) * 16; }
    else return;
    d[j] = f4_to_h4(__ldg(&s[j]));
}

// ===========================================================================
// CSR build
// ===========================================================================
__global__ void histall_k(int* __restrict__ bins,
                          const int* __restrict__ uir, const int* __restrict__ uic, int eui,
                          const int* __restrict__ ubr, const int* __restrict__ ubc, int eub,
                          const int* __restrict__ bir, int ebi) {
    int i = blockIdx.x * 256 + threadIdx.x;
    if (i < eui) {
        atomicAdd(&bins[B_UIU + __ldg(&uir[i])], 1);
        atomicAdd(&bins[B_UII + __ldg(&uic[i])], 1);
    } else if (i < eui + eub) {
        int j = i - eui;
        atomicAdd(&bins[B_UBU + __ldg(&ubr[j])], 1);
        atomicAdd(&bins[B_UBB + __ldg(&ubc[j])], 1);
    } else if (i < eui + eub + ebi) {
        int j = i - eui - eub;
        atomicAdd(&bins[B_BIB + __ldg(&bir[j])], 1);
    }
}

__global__ void scan_blk_k(const int* __restrict__ bins, int* __restrict__ rowptr,
                           int* __restrict__ bsums, int n) {
    __shared__ int sh[256];
    int t = threadIdx.x;
    int base = blockIdx.x * 1024 + t * 4;
    int v[4], s = 0;
    #pragma unroll
    for (int i = 0; i < 4; i++) {
        v[i] = (base + i < n) ? bins[base + i] : 0;
        s += v[i];
    }
    sh[t] = s;
    __syncthreads();
    for (int off = 1; off < 256; off <<= 1) {
        int x = (t >= off) ? sh[t - off] : 0;
        __syncthreads();
        sh[t] += x;
        __syncthreads();
    }
    int run = sh[t] - s;
    #pragma unroll
    for (int i = 0; i < 4; i++) {
        if (base + i < n) rowptr[base + i] = run;
        run += v[i];
    }
    if (t == 255) bsums[blockIdx.x] = sh[255];
}

__global__ void scan_top_k(int* __restrict__ bsums, int nb, int* __restrict__ rowptr) {
    __shared__ int sh[512];
    int t = threadIdx.x;
    int v = (t < nb) ? bsums[t] : 0;
    sh[t] = v;
    __syncthreads();
    for (int off = 1; off < 512; off <<= 1) {
        int x = (t >= off) ? sh[t - off] : 0;
        __syncthreads();
        sh[t] += x;
        __syncthreads();
    }
    if (t < nb) bsums[t] = sh[t] - v;
    if (t == 0) rowptr[TOTBINS] = sh[511];
}

__global__ void scan_add_k(int* __restrict__ rowptr, int* __restrict__ cursor,
                           const int* __restrict__ bsums, int n) {
    int t = threadIdx.x;
    int off = __ldg(&bsums[blockIdx.x]);
    int base = blockIdx.x * 1024 + t * 4;
    #pragma unroll
    for (int i = 0; i < 4; i++) {
        int idx = base + i;
        if (idx < n) {
            int r = rowptr[idx] + off;
            rowptr[idx] = r;
            cursor[idx] = r;
        }
    }
}

__global__ void ssortall_k(int* __restrict__ sorted, int* __restrict__ cursor,
                           const int* __restrict__ uir, const int* __restrict__ uic, int eui,
                           const int* __restrict__ ubr, const int* __restrict__ ubc, int eub,
                           const int* __restrict__ bir, const int* __restrict__ bic, int ebi) {
    int i = blockIdx.x * 256 + threadIdx.x;
    if (i < eui) {
        int a = __ldg(&uir[i]), b = __ldg(&uic[i]);
        sorted[atomicAdd(&cursor[B_UIU + a], 1)] = b;
        sorted[atomicAdd(&cursor[B_UII + b], 1)] = a;
    } else if (i < eui + eub) {
        int j = i - eui;
        int a = __ldg(&ubr[j]), b = __ldg(&ubc[j]);
        sorted[atomicAdd(&cursor[B_UBU + a], 1)] = b;
        sorted[atomicAdd(&cursor[B_UBB + b], 1)] = a;
    } else if (i < eui + eub + ebi) {
        int j = i - eui - eub;
        sorted[atomicAdd(&cursor[B_BIB + __ldg(&bir[j])], 1)] = __ldg(&bic[j]);
    }
}

// ===========================================================================
// Half-payload row gather: 16 lanes per row, lane owns 4 halves (8B).
// 4x-unrolled for MLP; accumulation in fp32.
// ===========================================================================
__device__ __forceinline__ float4 row_gather_h(const uint2* __restrict__ src,
                                               const int* __restrict__ sorted,
                                               int e, int e1, int lane) {
    float4 a0 = make_float4(0.f, 0.f, 0.f, 0.f);
    float4 a1 = make_float4(0.f, 0.f, 0.f, 0.f);
    for (; e + 4 <= e1; e += 4) {
        int s0 = __ldg(&sorted[e + 0]);
        int s1 = __ldg(&sorted[e + 1]);
        int s2 = __ldg(&sorted[e + 2]);
        int s3 = __ldg(&sorted[e + 3]);
        uint2 v0 = __ldg(&src[(size_t)s0 * 16 + lane]);
        uint2 v1 = __ldg(&src[(size_t)s1 * 16 + lane]);
        uint2 v2 = __ldg(&src[(size_t)s2 * 16 + lane]);
        uint2 v3 = __ldg(&src[(size_t)s3 * 16 + lane]);
        hacc4(a0, v0); hacc4(a1, v1); hacc4(a0, v2); hacc4(a1, v3);
    }
    for (; e < e1; e++) {
        int s = __ldg(&sorted[e]);
        hacc4(a0, __ldg(&src[(size_t)s * 16 + lane]));
    }
    a0.x += a1.x; a0.y += a1.y; a0.z += a1.z; a0.w += a1.w;
    return a0;
}

__device__ __forceinline__ float norm_inv16(float4 acc, unsigned gmask) {
    float ss = acc.x * acc.x + acc.y * acc.y + acc.z * acc.z + acc.w * acc.w;
    #pragma unroll
    for (int o = 8; o; o >>= 1) ss += __shfl_xor_sync(gmask, ss, o);
    return 1.0f / fmaxf(sqrtf(ss), 1e-12f);
}

// ---- layer-1: feat(half) = gather; acc(fp32) = base + norm(feat) ----------
struct L1Params {
    const uint2*  src[4];     // half feature tables
    const float4* base[4];    // fp32 original features
    uint2*        feat[4];    // half layer-1 sums
    float4*       acc[4];     // fp32 accumulators
    int           segBase[4];
};

__global__ void gather_l1_k(L1Params p, const int* __restrict__ rowptr,
                            const int* __restrict__ sorted, int nRows) {
    int g = (blockIdx.x * 256 + threadIdx.x) >> 4;
    if (g >= nRows) return;
    int lane = threadIdx.x & 15;
    unsigned gmask = 0xFFFFu << (threadIdx.x & 16);

    int seg = (g < B_UII) ? 0 : (g < B_UBU) ? 1 : (g < B_UBB) ? 2 : 3;
    int r = g - p.segBase[seg];

    int e  = __ldg(&rowptr[g]);
    int e1 = __ldg(&rowptr[g + 1]);
    float4 acc = row_gather_h(p.src[seg], sorted, e, e1, lane);

    p.feat[seg][(size_t)r * 16 + lane] = f4_to_h4(acc);

    float inv = norm_inv16(acc, gmask);
    float4 b = __ldg(&p.base[seg][(size_t)r * 16 + lane]);
    p.acc[seg][(size_t)r * 16 + lane] =
        make_float4(b.x + acc.x * inv, b.y + acc.y * inv,
                    b.z + acc.z * inv, b.w + acc.w * inv);
}

// ---- layer-2: out = acc + norm(gather(feat)); seg1 writes half IL_i -------
struct L2Params {
    const uint2*  src[4];     // half layer-1 feats
    const float4* base[4];    // fp32 accumulators
    float4*       dstF[4];    // fp32 outputs (null for seg 1)
    uint2*        dstH;       // half IL_i (seg 1 only)
    int           stride[4];
    int           off[4];
    int           segBase[4];
};

__global__ void gather_l2_k(L2Params p, const int* __restrict__ rowptr,
                            const int* __restrict__ sorted, int nRows) {
    int g = (blockIdx.x * 256 + threadIdx.x) >> 4;
    if (g >= nRows) return;
    int lane = threadIdx.x & 15;
    unsigned gmask = 0xFFFFu << (threadIdx.x & 16);

    int seg = (g < B_UII) ? 0 : (g < B_UBU) ? 1 : (g < B_UBB) ? 2 : 3;
    int r = g - p.segBase[seg];

    int e  = __ldg(&rowptr[g]);
    int e1 = __ldg(&rowptr[g + 1]);
    float4 acc = row_gather_h(p.src[seg], sorted, e, e1, lane);

    float inv = norm_inv16(acc, gmask);
    float4 b = __ldg(&p.base[seg][(size_t)r * 16 + lane]);
    float4 out = make_float4(b.x + acc.x * inv, b.y + acc.y * inv,
                             b.z + acc.z * inv, b.w + acc.w * inv);
    if (seg == 1) {
        p.dstH[(size_t)r * 16 + lane] = f4_to_h4(out);
    } else {
        p.dstF[seg][(size_t)r * p.stride[seg] + p.off[seg] + lane] = out;
    }
}

// ---- bi: out(fp32) = (1/(deg+1e-8)) * gather(IL_i half) -------------------
__global__ void gatherw_k(float4* __restrict__ dst, int dstStride4, int dstOff4,
                          const uint2* __restrict__ src,
                          const int* __restrict__ rowptr, int binbase,
                          const int* __restrict__ sorted, int nRows) {
    int g = (blockIdx.x * 256 + threadIdx.x) >> 4;
    if (g >= nRows) return;
    int lane = threadIdx.x & 15;

    int e  = __ldg(&rowptr[binbase + g]);
    int e1 = __ldg(&rowptr[binbase + g + 1]);
    float w = 1.0f / ((float)(e1 - e) + 1e-8f);
    float4 acc = row_gather_h(src, sorted, e, e1, lane);
    dst[(size_t)g * dstStride4 + dstOff4 + lane] =
        make_float4(acc.x * w, acc.y * w, acc.z * w, acc.w * w);
}

// ===========================================================================
extern "C" void kernel_launch(void* const* d_in, const int* in_sizes, int n_in,
                              void* d_out, int out_size) {
    const float* usersF   = (const float*)d_in[0];
    const float* itemsF   = (const float*)d_in[1];
    const float* bundlesF = (const float*)d_in[2];
    const int* ui_row = (const int*)d_in[3];
    const int* ui_col = (const int*)d_in[4];
    const int* ub_row = (const int*)d_in[5];
    const int* ub_col = (const int*)d_in[6];
    const int* bi_row = (const int*)d_in[7];
    const int* bi_col = (const int*)d_in[8];
    const int eui = in_sizes[3];
    const int eub = in_sizes[5];
    const int ebi = in_sizes[7];

    __half* H = nullptr;  float* F = nullptr;
    cudaGetSymbolAddress((void**)&H, g_halves);
    cudaGetSymbolAddress((void**)&F, g_floats);
    int *bins, *rowptr, *cursor, *sorted, *bsums;
    cudaGetSymbolAddress((void**)&bins,   g_bins);
    cudaGetSymbolAddress((void**)&rowptr, g_rowptr);
    cudaGetSymbolAddress((void**)&cursor, g_cursor);
    cudaGetSymbolAddress((void**)&sorted, g_sorted);
    cudaGetSymbolAddress((void**)&bsums,  g_bsums);

    uint2* hUsers = (uint2*)(H + H_USERS);
    uint2* hItems = (uint2*)(H + H_ITEMS);
    uint2* hBund  = (uint2*)(H + H_BUND);
    uint2* hFU1ui = (uint2*)(H + H_FU1UI);
    uint2* hFI1ui = (uint2*)(H + H_FI1UI);
    uint2* hFU1ub = (uint2*)(H + H_FU1UB);
    uint2* hFB1ub = (uint2*)(H + H_FB1UB);
    uint2* hILi   = (uint2*)(H + H_ILI);

    float4* accUil = (float4*)(F + F_ACCUIL);
    float4* accI   = (float4*)(F + F_ACCI);
    float4* accUbl = (float4*)(F + F_ACCUBL);
    float4* accB   = (float4*)(F + F_ACCB);

    float4* outU = (float4*)d_out;                               // users  [NU,128]
    float4* outB = (float4*)((float*)d_out + (size_t)NU * 128);  // bundles [NB,128]

    const int eall = eui + eub + ebi;

    // ---------------- fp16 conversion + CSR build ---------------------------
    cudaMemsetAsync(bins, 0, TOTBINS * sizeof(int));
    cvt_k<<<div_up((long long)(NU + NI + NB) * 16, 256), 256>>>(
        (const float4*)usersF, (const float4*)itemsF, (const float4*)bundlesF,
        hUsers, hItems, hBund);
    histall_k<<<div_up(eall, 256), 256>>>(bins, ui_row, ui_col, eui,
                                          ub_row, ub_col, eub, bi_row, ebi);
    scan_blk_k<<<SCAN_NBLK, 256>>>(bins, rowptr, bsums, TOTBINS);
    scan_top_k<<<1, 512>>>(bsums, SCAN_NBLK, rowptr);
    scan_add_k<<<SCAN_NBLK, 256>>>(rowptr, cursor, bsums, TOTBINS);
    ssortall_k<<<div_up(eall, 256), 256>>>(sorted, cursor, ui_row, ui_col, eui,
                                           ub_row, ub_col, eub, bi_row, bi_col, ebi);

    // ---------------- layer-1 (one launch, 4 segments) ----------------------
    L1Params p1;
    p1.src[0] = hItems; p1.base[0] = (const float4*)usersF;
    p1.feat[0] = hFU1ui; p1.acc[0] = accUil;
    p1.src[1] = hUsers; p1.base[1] = (const float4*)itemsF;
    p1.feat[1] = hFI1ui; p1.acc[1] = accI;
    p1.src[2] = hBund;  p1.base[2] = (const float4*)usersF;
    p1.feat[2] = hFU1ub; p1.acc[2] = accUbl;
    p1.src[3] = hUsers; p1.base[3] = (const float4*)bundlesF;
    p1.feat[3] = hFB1ub; p1.acc[3] = accB;
    p1.segBase[0] = B_UIU; p1.segBase[1] = B_UII;
    p1.segBase[2] = B_UBU; p1.segBase[3] = B_UBB;
    gather_l1_k<<<div_up((long long)NROWS_PROP * 16, 256), 256>>>(
        p1, rowptr, sorted, NROWS_PROP);

    // ---------------- layer-2 (one launch, 4 segments) ----------------------
    L2Params p2;
    p2.src[0] = hFI1ui; p2.base[0] = accUil;
    p2.dstF[0] = outU; p2.stride[0] = 32; p2.off[0] = 0;     // IL_u -> out[:,0:64]
    p2.src[1] = hFU1ui; p2.base[1] = accI;
    p2.dstF[1] = nullptr; p2.stride[1] = 16; p2.off[1] = 0;  // IL_i -> hILi
    p2.src[2] = hFB1ub; p2.base[2] = accUbl;
    p2.dstF[2] = outU; p2.stride[2] = 32; p2.off[2] = 16;    // BL_u -> out[:,64:128]
    p2.src[3] = hFU1ub; p2.base[3] = accB;
    p2.dstF[3] = outB; p2.stride[3] = 32; p2.off[3] = 16;    // BL_b -> out[NU+:,64:128]
    p2.dstH = hILi;
    p2.segBase[0] = B_UIU; p2.segBase[1] = B_UII;
    p2.segBase[2] = B_UBU; p2.segBase[3] = B_UBB;
    gather_l2_k<<<div_up((long long)NROWS_PROP * 16, 256), 256>>>(
        p2, rowptr, sorted, NROWS_PROP);

    // ---------------- IL_b = rownorm(bi) @ IL_items -> out[NU+:,0:64] -------
    gatherw_k<<<div_up((long long)NB * 16, 256), 256>>>(
        outB, 32, 0, hILi, rowptr, B_BIB, sorted, NB);
}

// round 15
// speedup vs baseline: 1.0695x; 1.0695x over previous
#include <cuda_runtime.h>
#include <cuda_fp16.h>

// ---------------------------------------------------------------------------
// CrossCBR propagation, D=64, num_layers=2 (fixed by setup_inputs).
// CSR-gather, fp16 payload, MLP-restructured gathers:
//   - 8 lanes per destination row, one uint4 (8 halves) per lane
//   - edge indices batch-loaded coalesced, broadcast via shuffle
//   - predicated 8-wide batches: every row runs at MLP=8 per lane
//   - all accumulation / norms / additive bases in fp32
// ---------------------------------------------------------------------------

#define NU 100000
#define NI 200000
#define NB 50000

#define B_UIU 0
#define B_UII 100000
#define B_UBU 300000
#define B_UBB 400000
#define B_BIB 450000
#define NROWS_PROP 450000
#define TOTBINS 500000
#define TOTEDGE 4000000

#define SCAN_NBLK 489     // ceil(500000/1024)

// ---- half arena offsets (half units; all multiples of 8 for uint4) --------
#define H_USERS  0UL
#define H_ITEMS  6400000UL
#define H_BUND   19200000UL
#define H_FU1UI  22400000UL
#define H_FI1UI  28800000UL
#define H_FU1UB  41600000UL
#define H_FB1UB  48000000UL
#define H_ILI    51200000UL
#define HALF_TOTAL 64000000UL

// ---- float arena offsets (fp32 accumulators) ------------------------------
#define F_ACCUIL 0UL
#define F_ACCI   6400000UL
#define F_ACCUBL 19200000UL
#define F_ACCB   25600000UL
#define FLOAT_TOTAL 28800000UL

__device__ __align__(16) __half g_halves[HALF_TOTAL];
__device__ __align__(16) float  g_floats[FLOAT_TOTAL];
__device__ int    g_bins[TOTBINS];
__device__ int    g_rowptr[TOTBINS + 1];
__device__ int    g_cursor[TOTBINS];
__device__ int    g_sorted[TOTEDGE];
__device__ int    g_bsums[512];

static inline int div_up(long long a, int b) { return (int)((a + b - 1) / b); }

// ---- pack/unpack helpers --------------------------------------------------
__device__ __forceinline__ uint2 f4_to_h4(float4 v) {
    __half2 h0 = __floats2half2_rn(v.x, v.y);
    __half2 h1 = __floats2half2_rn(v.z, v.w);
    uint2 o;
    o.x = *reinterpret_cast<unsigned*>(&h0);
    o.y = *reinterpret_cast<unsigned*>(&h1);
    return o;
}

__device__ __forceinline__ uint4 f8_to_h8(const float a[8]) {
    uint4 o;
    __half2 h0 = __floats2half2_rn(a[0], a[1]);
    __half2 h1 = __floats2half2_rn(a[2], a[3]);
    __half2 h2 = __floats2half2_rn(a[4], a[5]);
    __half2 h3 = __floats2half2_rn(a[6], a[7]);
    o.x = *reinterpret_cast<unsigned*>(&h0);
    o.y = *reinterpret_cast<unsigned*>(&h1);
    o.z = *reinterpret_cast<unsigned*>(&h2);
    o.w = *reinterpret_cast<unsigned*>(&h3);
    return o;
}

// ===========================================================================
// fp32 -> fp16 conversion of the three input tables (one launch)
// ===========================================================================
__global__ void cvt_k(const float4* __restrict__ u, const float4* __restrict__ it,
                      const float4* __restrict__ b,
                      uint2* __restrict__ hu, uint2* __restrict__ hi,
                      uint2* __restrict__ hb) {
    int i = blockIdx.x * 256 + threadIdx.x;
    const float4* s; uint2* d; int j;
    if (i < NU * 16)                  { s = u;  d = hu; j = i; }
    else if (i < (NU + NI) * 16)      { s = it; d = hi; j = i - NU * 16; }
    else if (i < (NU + NI + NB) * 16) { s = b;  d = hb; j = i - (NU + NI) * 16; }
    else return;
    d[j] = f4_to_h4(__ldg(&s[j]));
}

// ===========================================================================
// CSR build
// ===========================================================================
__global__ void histall_k(int* __restrict__ bins,
                          const int* __restrict__ uir, const int* __restrict__ uic, int eui,
                          const int* __restrict__ ubr, const int* __restrict__ ubc, int eub,
                          const int* __restrict__ bir, int ebi) {
    int i = blockIdx.x * 256 + threadIdx.x;
    if (i < eui) {
        atomicAdd(&bins[B_UIU + __ldg(&uir[i])], 1);
        atomicAdd(&bins[B_UII + __ldg(&uic[i])], 1);
    } else if (i < eui + eub) {
        int j = i - eui;
        atomicAdd(&bins[B_UBU + __ldg(&ubr[j])], 1);
        atomicAdd(&bins[B_UBB + __ldg(&ubc[j])], 1);
    } else if (i < eui + eub + ebi) {
        int j = i - eui - eub;
        atomicAdd(&bins[B_BIB + __ldg(&bir[j])], 1);
    }
}

__global__ void scan_blk_k(const int* __restrict__ bins, int* __restrict__ rowptr,
                           int* __restrict__ bsums, int n) {
    __shared__ int sh[256];
    int t = threadIdx.x;
    int base = blockIdx.x * 1024 + t * 4;
    int v[4], s = 0;
    #pragma unroll
    for (int i = 0; i < 4; i++) {
        v[i] = (base + i < n) ? bins[base + i] : 0;
        s += v[i];
    }
    sh[t] = s;
    __syncthreads();
    for (int off = 1; off < 256; off <<= 1) {
        int x = (t >= off) ? sh[t - off] : 0;
        __syncthreads();
        sh[t] += x;
        __syncthreads();
    }
    int run = sh[t] - s;
    #pragma unroll
    for (int i = 0; i < 4; i++) {
        if (base + i < n) rowptr[base + i] = run;
        run += v[i];
    }
    if (t == 255) bsums[blockIdx.x] = sh[255];
}

__global__ void scan_top_k(int* __restrict__ bsums, int nb, int* __restrict__ rowptr) {
    __shared__ int sh[512];
    int t = threadIdx.x;
    int v = (t < nb) ? bsums[t] : 0;
    sh[t] = v;
    __syncthreads();
    for (int off = 1; off < 512; off <<= 1) {
        int x = (t >= off) ? sh[t - off] : 0;
        __syncthreads();
        sh[t] += x;
        __syncthreads();
    }
    if (t < nb) bsums[t] = sh[t] - v;
    if (t == 0) rowptr[TOTBINS] = sh[511];
}

__global__ void scan_add_k(int* __restrict__ rowptr, int* __restrict__ cursor,
                           const int* __restrict__ bsums, int n) {
    int t = threadIdx.x;
    int off = __ldg(&bsums[blockIdx.x]);
    int base = blockIdx.x * 1024 + t * 4;
    #pragma unroll
    for (int i = 0; i < 4; i++) {
        int idx = base + i;
        if (idx < n) {
            int r = rowptr[idx] + off;
            rowptr[idx] = r;
            cursor[idx] = r;
        }
    }
}

__global__ void ssortall_k(int* __restrict__ sorted, int* __restrict__ cursor,
                           const int* __restrict__ uir, const int* __restrict__ uic, int eui,
                           const int* __restrict__ ubr, const int* __restrict__ ubc, int eub,
                           const int* __restrict__ bir, const int* __restrict__ bic, int ebi) {
    int i = blockIdx.x * 256 + threadIdx.x;
    if (i < eui) {
        int a = __ldg(&uir[i]), b = __ldg(&uic[i]);
        sorted[atomicAdd(&cursor[B_UIU + a], 1)] = b;
        sorted[atomicAdd(&cursor[B_UII + b], 1)] = a;
    } else if (i < eui + eub) {
        int j = i - eui;
        int a = __ldg(&ubr[j]), b = __ldg(&ubc[j]);
        sorted[atomicAdd(&cursor[B_UBU + a], 1)] = b;
        sorted[atomicAdd(&cursor[B_UBB + b], 1)] = a;
    } else if (i < eui + eub + ebi) {
        int j = i - eui - eub;
        sorted[atomicAdd(&cursor[B_BIB + __ldg(&bir[j])], 1)] = __ldg(&bic[j]);
    }
}

// ===========================================================================
// 8-lane row gather, MLP=8:
//   - lane l of the 8-lane group owns halves [8l..8l+8) of the 64-wide row
//   - per batch of 8 edges: one coalesced index load, shuffle-broadcast,
//     8 independent uint4 loads issued back-to-back (predicated; invalid
//     slots clamp to row 0 which stays L1-resident)
// ===========================================================================
__device__ __forceinline__ void row_gather8(float acc[8],
        const uint4* __restrict__ src, const int* __restrict__ sorted,
        int e, int e1, int lane8, int base8, unsigned mask8) {
    #pragma unroll
    for (int k = 0; k < 8; k++) acc[k] = 0.f;
    for (; e < e1; e += 8) {
        int m = e1 - e;
        int idx = (lane8 < m) ? __ldg(&sorted[e + lane8]) : 0;
        #pragma unroll
        for (int j = 0; j < 8; j++) {
            int s = __shfl_sync(mask8, idx, base8 + j);
            bool valid = (j < m);
            uint4 v = __ldg(&src[(size_t)(valid ? s : 0) * 8 + lane8]);
            if (valid) {
                __half2* h = reinterpret_cast<__half2*>(&v);
                #pragma unroll
                for (int k = 0; k < 4; k++) {
                    float2 f = __half22float2(h[k]);
                    acc[2 * k]     += f.x;
                    acc[2 * k + 1] += f.y;
                }
            }
        }
    }
}

__device__ __forceinline__ float norm_inv8(const float acc[8], unsigned mask8) {
    float ss = 0.f;
    #pragma unroll
    for (int k = 0; k < 8; k++) ss += acc[k] * acc[k];
    #pragma unroll
    for (int o = 4; o; o >>= 1) ss += __shfl_xor_sync(mask8, ss, o);
    return 1.0f / fmaxf(sqrtf(ss), 1e-12f);
}

// ---- layer-1: feat(half) = gather; acc(fp32) = base + norm(gather) --------
struct L1Params {
    const uint4*  src[4];
    const float4* base[4];
    uint4*        feat[4];
    float4*       acc[4];
    int           segBase[4];
};

__global__ void __launch_bounds__(256) gather_l1_k(
        L1Params p, const int* __restrict__ rowptr,
        const int* __restrict__ sorted, int nRows) {
    int g = (blockIdx.x * 256 + threadIdx.x) >> 3;
    if (g >= nRows) return;
    int wl = threadIdx.x & 31;
    int lane8 = wl & 7;
    int base8 = wl & 24;
    unsigned mask8 = 0xFFu << base8;

    int seg = (g < B_UII) ? 0 : (g < B_UBU) ? 1 : (g < B_UBB) ? 2 : 3;
    int r = g - p.segBase[seg];

    int e  = __ldg(&rowptr[g]);
    int e1 = __ldg(&rowptr[g + 1]);
    float acc[8];
    row_gather8(acc, p.src[seg], sorted, e, e1, lane8, base8, mask8);

    p.feat[seg][(size_t)r * 8 + lane8] = f8_to_h8(acc);

    float inv = norm_inv8(acc, mask8);
    const float4* brow = p.base[seg] + (size_t)r * 16 + lane8 * 2;
    float4 b0 = __ldg(brow);
    float4 b1 = __ldg(brow + 1);
    float4* arow = p.acc[seg] + (size_t)r * 16 + lane8 * 2;
    arow[0] = make_float4(b0.x + acc[0] * inv, b0.y + acc[1] * inv,
                          b0.z + acc[2] * inv, b0.w + acc[3] * inv);
    arow[1] = make_float4(b1.x + acc[4] * inv, b1.y + acc[5] * inv,
                          b1.z + acc[6] * inv, b1.w + acc[7] * inv);
}

// ---- layer-2: out = acc + norm(gather(feat)); seg1 writes half IL_i -------
struct L2Params {
    const uint4*  src[4];
    const float4* base[4];
    float4*       dstF[4];   // fp32 outputs (unused for seg 1)
    uint4*        dstH;      // half IL_i (seg 1)
    int           stride[4]; // in float4 units
    int           off[4];
    int           segBase[4];
};

__global__ void __launch_bounds__(256) gather_l2_k(
        L2Params p, const int* __restrict__ rowptr,
        const int* __restrict__ sorted, int nRows) {
    int g = (blockIdx.x * 256 + threadIdx.x) >> 3;
    if (g >= nRows) return;
    int wl = threadIdx.x & 31;
    int lane8 = wl & 7;
    int base8 = wl & 24;
    unsigned mask8 = 0xFFu << base8;

    int seg = (g < B_UII) ? 0 : (g < B_UBU) ? 1 : (g < B_UBB) ? 2 : 3;
    int r = g - p.segBase[seg];

    int e  = __ldg(&rowptr[g]);
    int e1 = __ldg(&rowptr[g + 1]);
    float acc[8];
    row_gather8(acc, p.src[seg], sorted, e, e1, lane8, base8, mask8);

    float inv = norm_inv8(acc, mask8);
    const float4* brow = p.base[seg] + (size_t)r * 16 + lane8 * 2;
    float4 b0 = __ldg(brow);
    float4 b1 = __ldg(brow + 1);
    float o[8];
    o[0] = b0.x + acc[0] * inv; o[1] = b0.y + acc[1] * inv;
    o[2] = b0.z + acc[2] * inv; o[3] = b0.w + acc[3] * inv;
    o[4] = b1.x + acc[4] * inv; o[5] = b1.y + acc[5] * inv;
    o[6] = b1.z + acc[6] * inv; o[7] = b1.w + acc[7] * inv;

    if (seg == 1) {
        p.dstH[(size_t)r * 8 + lane8] = f8_to_h8(o);
    } else {
        float4* drow = p.dstF[seg] + (size_t)r * p.stride[seg] + p.off[seg] + lane8 * 2;
        drow[0] = make_float4(o[0], o[1], o[2], o[3]);
        drow[1] = make_float4(o[4], o[5], o[6], o[7]);
    }
}

// ---- bi: out(fp32) = (1/(deg+1e-8)) * gather(IL_i half) -------------------
__global__ void __launch_bounds__(256) gatherw_k(
        float4* __restrict__ dst, int dstStride4, int dstOff4,
        const uint4* __restrict__ src,
        const int* __restrict__ rowptr, int binbase,
        const int* __restrict__ sorted, int nRows) {
    int g = (blockIdx.x * 256 + threadIdx.x) >> 3;
    if (g >= nRows) return;
    int wl = threadIdx.x & 31;
    int lane8 = wl & 7;
    int base8 = wl & 24;
    unsigned mask8 = 0xFFu << base8;

    int e  = __ldg(&rowptr[binbase + g]);
    int e1 = __ldg(&rowptr[binbase + g + 1]);
    float w = 1.0f / ((float)(e1 - e) + 1e-8f);
    float acc[8];
    row_gather8(acc, src, sorted, e, e1, lane8, base8, mask8);

    float4* drow = dst + (size_t)g * dstStride4 + dstOff4 + lane8 * 2;
    drow[0] = make_float4(acc[0] * w, acc[1] * w, acc[2] * w, acc[3] * w);
    drow[1] = make_float4(acc[4] * w, acc[5] * w, acc[6] * w, acc[7] * w);
}

// ===========================================================================
extern "C" void kernel_launch(void* const* d_in, const int* in_sizes, int n_in,
                              void* d_out, int out_size) {
    const float* usersF   = (const float*)d_in[0];
    const float* itemsF   = (const float*)d_in[1];
    const float* bundlesF = (const float*)d_in[2];
    const int* ui_row = (const int*)d_in[3];
    const int* ui_col = (const int*)d_in[4];
    const int* ub_row = (const int*)d_in[5];
    const int* ub_col = (const int*)d_in[6];
    const int* bi_row = (const int*)d_in[7];
    const int* bi_col = (const int*)d_in[8];
    const int eui = in_sizes[3];
    const int eub = in_sizes[5];
    const int ebi = in_sizes[7];

    __half* H = nullptr;  float* F = nullptr;
    cudaGetSymbolAddress((void**)&H, g_halves);
    cudaGetSymbolAddress((void**)&F, g_floats);
    int *bins, *rowptr, *cursor, *sorted, *bsums;
    cudaGetSymbolAddress((void**)&bins,   g_bins);
    cudaGetSymbolAddress((void**)&rowptr, g_rowptr);
    cudaGetSymbolAddress((void**)&cursor, g_cursor);
    cudaGetSymbolAddress((void**)&sorted, g_sorted);
    cudaGetSymbolAddress((void**)&bsums,  g_bsums);

    uint4* hUsers = (uint4*)(H + H_USERS);
    uint4* hItems = (uint4*)(H + H_ITEMS);
    uint4* hBund  = (uint4*)(H + H_BUND);
    uint4* hFU1ui = (uint4*)(H + H_FU1UI);
    uint4* hFI1ui = (uint4*)(H + H_FI1UI);
    uint4* hFU1ub = (uint4*)(H + H_FU1UB);
    uint4* hFB1ub = (uint4*)(H + H_FB1UB);
    uint4* hILi   = (uint4*)(H + H_ILI);

    float4* accUil = (float4*)(F + F_ACCUIL);
    float4* accI   = (float4*)(F + F_ACCI);
    float4* accUbl = (float4*)(F + F_ACCUBL);
    float4* accB   = (float4*)(F + F_ACCB);

    float4* outU = (float4*)d_out;
    float4* outB = (float4*)((float*)d_out + (size_t)NU * 128);

    const int eall = eui + eub + ebi;

    // ---------------- fp16 conversion + CSR build ---------------------------
    cudaMemsetAsync(bins, 0, TOTBINS * sizeof(int));
    cvt_k<<<div_up((long long)(NU + NI + NB) * 16, 256), 256>>>(
        (const float4*)usersF, (const float4*)itemsF, (const float4*)bundlesF,
        (uint2*)hUsers, (uint2*)hItems, (uint2*)hBund);
    histall_k<<<div_up(eall, 256), 256>>>(bins, ui_row, ui_col, eui,
                                          ub_row, ub_col, eub, bi_row, ebi);
    scan_blk_k<<<SCAN_NBLK, 256>>>(bins, rowptr, bsums, TOTBINS);
    scan_top_k<<<1, 512>>>(bsums, SCAN_NBLK, rowptr);
    scan_add_k<<<SCAN_NBLK, 256>>>(rowptr, cursor, bsums, TOTBINS);
    ssortall_k<<<div_up(eall, 256), 256>>>(sorted, cursor, ui_row, ui_col, eui,
                                           ub_row, ub_col, eub, bi_row, bi_col, ebi);

    // ---------------- layer-1 (one launch, 4 segments) ----------------------
    L1Params p1;
    p1.src[0] = hItems; p1.base[0] = (const float4*)usersF;
    p1.feat[0] = hFU1ui; p1.acc[0] = accUil;
    p1.src[1] = hUsers; p1.base[1] = (const float4*)itemsF;
    p1.feat[1] = hFI1ui; p1.acc[1] = accI;
    p1.src[2] = hBund;  p1.base[2] = (const float4*)usersF;
    p1.feat[2] = hFU1ub; p1.acc[2] = accUbl;
    p1.src[3] = hUsers; p1.base[3] = (const float4*)bundlesF;
    p1.feat[3] = hFB1ub; p1.acc[3] = accB;
    p1.segBase[0] = B_UIU; p1.segBase[1] = B_UII;
    p1.segBase[2] = B_UBU; p1.segBase[3] = B_UBB;
    gather_l1_k<<<div_up((long long)NROWS_PROP * 8, 256), 256>>>(
        p1, rowptr, sorted, NROWS_PROP);

    // ---------------- layer-2 (one launch, 4 segments) ----------------------
    L2Params p2;
    p2.src[0] = hFI1ui; p2.base[0] = accUil;
    p2.dstF[0] = outU; p2.stride[0] = 32; p2.off[0] = 0;     // IL_u
    p2.src[1] = hFU1ui; p2.base[1] = accI;
    p2.dstF[1] = nullptr; p2.stride[1] = 16; p2.off[1] = 0;  // IL_i -> half
    p2.src[2] = hFB1ub; p2.base[2] = accUbl;
    p2.dstF[2] = outU; p2.stride[2] = 32; p2.off[2] = 16;    // BL_u
    p2.src[3] = hFU1ub; p2.base[3] = accB;
    p2.dstF[3] = outB; p2.stride[3] = 32; p2.off[3] = 16;    // BL_b
    p2.dstH = hILi;
    p2.segBase[0] = B_UIU; p2.segBase[1] = B_UII;
    p2.segBase[2] = B_UBU; p2.segBase[3] = B_UBB;
    gather_l2_k<<<div_up((long long)NROWS_PROP * 8, 256), 256>>>(
        p2, rowptr, sorted, NROWS_PROP);

    // ---------------- IL_b = rownorm(bi) @ IL_items -> out[NU+:,0:64] -------
    gatherw_k<<<div_up((long long)NB * 8, 256), 256>>>(
        outB, 32, 0, hILi, rowptr, B_BIB, sorted, NB);
}